// round 2
// baseline (speedup 1.0000x reference)
#include <cuda_runtime.h>

// ---------------------------------------------------------------------------
// LIF layer: out[b,t,h] = spikes of leaky integrate-and-fire driven by
// Wx[b,t,h] = sum_i x[b,t,i] * W[h,i]
//
// Round 1: fp32 SGEMM (128x128x8 register-blocked) -> scratch, then per-neuron
// sequential scan over T. fp32 everywhere: spike outputs are binary and the
// rel-err budget tolerates essentially no threshold flips, ruling out TF32.
// ---------------------------------------------------------------------------

static constexpr int Bb = 64;
static constexpr int Tt = 1000;
static constexpr int Ii = 1024;   // input dim (K)
static constexpr int Hh = 1024;   // hidden dim (N)
static constexpr int Mm = Bb * Tt;  // 64000 GEMM rows

// 262 MB scratch for Wx (allowed: __device__ global, no runtime alloc)
__device__ float g_Wx[(size_t)Mm * Hh];

#define BM 128
#define BN 128
#define BK 8
#define TM 8
#define TN 8

// C[m,n] = sum_k A[m,k] * B[n,k]   (A: MxK row-major, B: NxK row-major)
__global__ __launch_bounds__(256, 2) void sgemm_nt_kernel(
    const float* __restrict__ A, const float* __restrict__ Bw)
{
    __shared__ float As[BK][BM];
    __shared__ float Bs[BK][BN];

    const int bm = blockIdx.y * BM;
    const int bn = blockIdx.x * BN;
    const int tid = threadIdx.x;

    // global->smem load mapping: 128 rows x 8 cols per tile, one float4/thread
    const int lrow = tid >> 1;          // 0..127
    const int lcol = (tid & 1) * 4;     // 0 or 4

    // compute mapping: 16x16 threads, each 8x8 micro-tile
    const int tx = tid & 15;
    const int ty = tid >> 4;

    const float* Aptr = A + (size_t)(bm + lrow) * Ii + lcol;
    const float* Bptr = Bw + (size_t)(bn + lrow) * Ii + lcol;

    float acc[TM][TN];
#pragma unroll
    for (int i = 0; i < TM; i++)
#pragma unroll
        for (int j = 0; j < TN; j++) acc[i][j] = 0.0f;

    float4 a4 = *(const float4*)(Aptr);
    float4 b4 = *(const float4*)(Bptr);

    for (int k0 = 0; k0 < Ii; k0 += BK) {
        As[lcol + 0][lrow] = a4.x;
        As[lcol + 1][lrow] = a4.y;
        As[lcol + 2][lrow] = a4.z;
        As[lcol + 3][lrow] = a4.w;
        Bs[lcol + 0][lrow] = b4.x;
        Bs[lcol + 1][lrow] = b4.y;
        Bs[lcol + 2][lrow] = b4.z;
        Bs[lcol + 3][lrow] = b4.w;
        __syncthreads();

        // prefetch next k-tile while computing this one
        if (k0 + BK < Ii) {
            a4 = *(const float4*)(Aptr + k0 + BK);
            b4 = *(const float4*)(Bptr + k0 + BK);
        }

#pragma unroll
        for (int kk = 0; kk < BK; kk++) {
            float af[TM], bf[TN];
            // vector loads from smem
            float4 av0 = *(const float4*)(&As[kk][ty * TM + 0]);
            float4 av1 = *(const float4*)(&As[kk][ty * TM + 4]);
            float4 bv0 = *(const float4*)(&Bs[kk][tx * TN + 0]);
            float4 bv1 = *(const float4*)(&Bs[kk][tx * TN + 4]);
            af[0] = av0.x; af[1] = av0.y; af[2] = av0.z; af[3] = av0.w;
            af[4] = av1.x; af[5] = av1.y; af[6] = av1.z; af[7] = av1.w;
            bf[0] = bv0.x; bf[1] = bv0.y; bf[2] = bv0.z; bf[3] = bv0.w;
            bf[4] = bv1.x; bf[5] = bv1.y; bf[6] = bv1.z; bf[7] = bv1.w;
#pragma unroll
            for (int i = 0; i < TM; i++)
#pragma unroll
                for (int j = 0; j < TN; j++)
                    acc[i][j] = fmaf(af[i], bf[j], acc[i][j]);
        }
        __syncthreads();
    }

    // write Wx tile (float4 stores, coalesced within a row of 16 threads)
#pragma unroll
    for (int i = 0; i < TM; i++) {
        float* crow = g_Wx + (size_t)(bm + ty * TM + i) * Hh + bn + tx * TN;
        *(float4*)(crow + 0) = make_float4(acc[i][0], acc[i][1], acc[i][2], acc[i][3]);
        *(float4*)(crow + 4) = make_float4(acc[i][4], acc[i][5], acc[i][6], acc[i][7]);
    }
}

// one thread per (b, h) neuron chain; fully coalesced across h at each t
__global__ __launch_bounds__(256) void lif_scan_kernel(
    const float* __restrict__ alpha,
    const float* __restrict__ u0,
    const float* __restrict__ s0,
    float* __restrict__ out)
{
    const int g = blockIdx.x * blockDim.x + threadIdx.x;  // 0 .. B*H-1
    if (g >= Bb * Hh) return;
    const int h = g & (Hh - 1);
    const int b = g >> 10;

    const float AMIN = 0.81873075307798185867f;  // exp(-1/5)
    const float AMAX = 0.96078943915232320938f;  // exp(-1/25)

    float a = alpha[h];
    a = fminf(fmaxf(a, AMIN), AMAX);
    const float oma = 1.0f - a;

    float u = u0[g];
    float s = s0[g];

    const float* wxp = g_Wx + (size_t)b * Tt * Hh + h;
    float* op = out + (size_t)b * Tt * Hh + h;

#pragma unroll 4
    for (int t = 0; t < Tt; t++) {
        const float wx = wxp[(size_t)t * Hh];
        u = a * (u - s) + oma * wx;
        s = (u > 1.0f) ? 1.0f : 0.0f;
        op[(size_t)t * Hh] = s;
    }
}

extern "C" void kernel_launch(void* const* d_in, const int* in_sizes, int n_in,
                              void* d_out, int out_size)
{
    const float* x     = (const float*)d_in[0];  // [B, T, I]
    const float* W     = (const float*)d_in[1];  // [H, I]
    const float* alpha = (const float*)d_in[2];  // [H]
    const float* u0    = (const float*)d_in[3];  // [B, H]
    const float* s0    = (const float*)d_in[4];  // [B, H]
    float* out = (float*)d_out;                  // [B, T, H]

    (void)in_sizes; (void)n_in; (void)out_size;

    dim3 grid(Hh / BN, Mm / BM);   // (8, 500)
    sgemm_nt_kernel<<<grid, 256>>>(x, W);

    const int nthreads = Bb * Hh;  // 65536
    lif_scan_kernel<<<nthreads / 256, 256>>>(alpha, u0, s0, out);
}

// round 4
// speedup vs baseline: 1.0499x; 1.0499x over previous
#include <cuda_runtime.h>
#include <cstdint>

// ---------------------------------------------------------------------------
// LIF layer: Wx = x @ W^T via legacy mma.sync tf32x3-split GEMM (fp32-accurate,
// compiles under compute_103 — tcgen05 is unavailable in this harness),
// then per-neuron sequential LIF scan.
// ---------------------------------------------------------------------------

static constexpr int Bb = 64;
static constexpr int Tt = 1000;
static constexpr int Ii = 1024;    // K
static constexpr int Hh = 1024;    // N
static constexpr int Mm = Bb * Tt; // 64000

__device__ float g_Wx[(size_t)Mm * Hh];   // 262 MB scratch

// ----------------------------- GEMM config ---------------------------------
static constexpr int BM = 128;
static constexpr int BN = 128;
static constexpr int BK = 32;                  // fp32 elems per chunk
static constexpr int KSTEPS = BK / 8;          // 4 k8-steps per chunk
static constexpr int NCHUNK = Ii / BK;         // 32

// smem fragment layout per variant per k8-step:
//   float2 arr[128][5]   (index [row][tig], tig<4 used, 5th is padding)
//   arr[row][tig] = { M[row][k0+tig], M[row][k0+tig+4] }
static constexpr int ROW_BYTES  = 5 * 8;                // 40
static constexpr int STEP_BYTES = 128 * ROW_BYTES;      // 5120
static constexpr int VAR_BYTES  = KSTEPS * STEP_BYTES;  // 20480
static constexpr int V_AHI = 0;
static constexpr int V_ALO = 1 * VAR_BYTES;
static constexpr int V_BHI = 2 * VAR_BYTES;
static constexpr int V_BLO = 3 * VAR_BYTES;
static constexpr int BUFSZ = 4 * VAR_BYTES;             // 81920
static constexpr int SMEM_TOTAL = 2 * BUFSZ;            // 163840

__device__ __forceinline__ uint32_t f2tf32(float a) {
    uint32_t r;
    asm("cvt.rna.tf32.f32 %0, %1;" : "=r"(r) : "f"(a));
    return r;
}

__device__ __forceinline__ void mma_tf32(float* d, const uint32_t* a, const uint32_t* b) {
    asm volatile(
        "mma.sync.aligned.m16n8k8.row.col.f32.tf32.tf32.f32 "
        "{%0,%1,%2,%3}, {%4,%5,%6,%7}, {%8,%9}, {%0,%1,%2,%3};"
        : "+f"(d[0]), "+f"(d[1]), "+f"(d[2]), "+f"(d[3])
        : "r"(a[0]), "r"(a[1]), "r"(a[2]), "r"(a[3]), "r"(b[0]), "r"(b[1]));
}

__global__ __launch_bounds__(256, 1) void gemm_tf32x3_mma(
    const float* __restrict__ A, const float* __restrict__ Bw)
{
    extern __shared__ char smem[];
    const int tid  = threadIdx.x;
    const int wid  = tid >> 5;
    const int lane = tid & 31;
    const int grp  = lane >> 2;     // 0..7
    const int tig  = lane & 3;      // 0..3
    const int warp_m = wid & 1;     // 2 warps in M
    const int warp_n = wid >> 1;    // 4 warps in N
    const int m0w = warp_m * 64;
    const int n0w = warp_n * 32;
    const int bm = blockIdx.y * BM;
    const int bn = blockIdx.x * BN;

    float acc[4][4][4];
#pragma unroll
    for (int i = 0; i < 4; i++)
#pragma unroll
        for (int j = 0; j < 4; j++)
#pragma unroll
            for (int k = 0; k < 4; k++) acc[i][j][k] = 0.0f;

    // fill-thread coordinates: thread handles 4 float4 of A and 4 of B per chunk
    int fm[4], fkq[4];
#pragma unroll
    for (int i = 0; i < 4; i++) {
        int f = i * 256 + tid;
        fm[i]  = f >> 3;            // 0..127
        fkq[i] = (f & 7) * 4;       // 0,4,...,28
    }

    float4 va[4], vb[4];

    auto ldg_chunk = [&](int k0) {
#pragma unroll
        for (int i = 0; i < 4; i++) {
            va[i] = *(const float4*)(A  + (size_t)(bm + fm[i]) * Ii + k0 + fkq[i]);
            vb[i] = *(const float4*)(Bw + (size_t)(bn + fm[i]) * Ii + k0 + fkq[i]);
        }
    };

    auto sts_chunk = [&](int buf) {
        char* base = smem + buf * BUFSZ;
#pragma unroll
        for (int i = 0; i < 4; i++) {
            const int s    = fkq[i] >> 3;       // k8 step
            const int half = (fkq[i] >> 2) & 1; // .x or .y slot
            // byte offset of float2 cell [s][row][tig=j], component 'half'
            uint32_t cell = (uint32_t)(s * STEP_BYTES + fm[i] * ROW_BYTES + half * 4);
            const float av[4] = {va[i].x, va[i].y, va[i].z, va[i].w};
            const float bv[4] = {vb[i].x, vb[i].y, vb[i].z, vb[i].w};
#pragma unroll
            for (int j = 0; j < 4; j++) {
                uint32_t ah = f2tf32(av[j]);
                uint32_t al = f2tf32(av[j] - __uint_as_float(ah));
                uint32_t bh = f2tf32(bv[j]);
                uint32_t bl = f2tf32(bv[j] - __uint_as_float(bh));
                *(uint32_t*)(base + V_AHI + cell + j * 8) = ah;
                *(uint32_t*)(base + V_ALO + cell + j * 8) = al;
                *(uint32_t*)(base + V_BHI + cell + j * 8) = bh;
                *(uint32_t*)(base + V_BLO + cell + j * 8) = bl;
            }
        }
    };

    ldg_chunk(0);
    sts_chunk(0);
    __syncthreads();

    for (int c = 0; c < NCHUNK; c++) {
        const int cur = c & 1;
        const char* p = smem + cur * BUFSZ;

        if (c + 1 < NCHUNK) ldg_chunk((c + 1) * BK);  // prefetch overlaps MMA

#pragma unroll
        for (int s = 0; s < KSTEPS; s++) {
            const char* ps = p + s * STEP_BYTES;
            // B fragments: 4 n-tiles x {hi,lo}, 1 LDS.64 each
            uint32_t bh[4][2], bl[4][2];
#pragma unroll
            for (int nt = 0; nt < 4; nt++) {
                const int n = n0w + nt * 8 + grp;
                float2 h = *(const float2*)(ps + V_BHI + n * ROW_BYTES + tig * 8);
                float2 l = *(const float2*)(ps + V_BLO + n * ROW_BYTES + tig * 8);
                bh[nt][0] = __float_as_uint(h.x); bh[nt][1] = __float_as_uint(h.y);
                bl[nt][0] = __float_as_uint(l.x); bl[nt][1] = __float_as_uint(l.y);
            }
#pragma unroll
            for (int mt = 0; mt < 4; mt++) {
                const int m = m0w + mt * 16 + grp;
                float2 h0 = *(const float2*)(ps + V_AHI + m * ROW_BYTES + tig * 8);
                float2 h1 = *(const float2*)(ps + V_AHI + (m + 8) * ROW_BYTES + tig * 8);
                float2 l0 = *(const float2*)(ps + V_ALO + m * ROW_BYTES + tig * 8);
                float2 l1 = *(const float2*)(ps + V_ALO + (m + 8) * ROW_BYTES + tig * 8);
                uint32_t ah[4] = {__float_as_uint(h0.x), __float_as_uint(h1.x),
                                  __float_as_uint(h0.y), __float_as_uint(h1.y)};
                uint32_t al[4] = {__float_as_uint(l0.x), __float_as_uint(l1.x),
                                  __float_as_uint(l0.y), __float_as_uint(l1.y)};
#pragma unroll
                for (int nt = 0; nt < 4; nt++) {
                    mma_tf32(acc[mt][nt], ah, bh[nt]);   // hi*hi
                    mma_tf32(acc[mt][nt], ah, bl[nt]);   // hi*lo
                    mma_tf32(acc[mt][nt], al, bh[nt]);   // lo*hi
                }
            }
        }

        if (c + 1 < NCHUNK) sts_chunk(cur ^ 1);
        __syncthreads();
    }

    // epilogue: registers -> g_Wx (float2 stores, 32B segments per row)
#pragma unroll
    for (int mt = 0; mt < 4; mt++) {
#pragma unroll
        for (int nt = 0; nt < 4; nt++) {
            const int row = bm + m0w + mt * 16 + grp;
            const int col = bn + n0w + nt * 8 + tig * 2;
            *(float2*)&g_Wx[(size_t)row * Hh + col] =
                make_float2(acc[mt][nt][0], acc[mt][nt][1]);
            *(float2*)&g_Wx[(size_t)(row + 8) * Hh + col] =
                make_float2(acc[mt][nt][2], acc[mt][nt][3]);
        }
    }
}

// ------------------------------- LIF scan ------------------------------------
__global__ __launch_bounds__(256) void lif_scan_kernel(
    const float* __restrict__ alpha,
    const float* __restrict__ u0,
    const float* __restrict__ s0,
    float* __restrict__ out)
{
    const int g = blockIdx.x * blockDim.x + threadIdx.x;
    if (g >= Bb * Hh) return;
    const int h = g & (Hh - 1);
    const int b = g >> 10;

    const float AMIN = 0.81873075307798185867f;  // exp(-1/5)
    const float AMAX = 0.96078943915232320938f;  // exp(-1/25)

    float a = alpha[h];
    a = fminf(fmaxf(a, AMIN), AMAX);
    const float oma = 1.0f - a;

    float u = u0[g];
    float s = s0[g];

    const float* wxp = g_Wx + (size_t)b * Tt * Hh + h;
    float* op = out + (size_t)b * Tt * Hh + h;

#pragma unroll 8
    for (int t = 0; t < Tt; t++) {
        const float wx = wxp[(size_t)t * Hh];
        u = a * (u - s) + oma * wx;
        s = (u > 1.0f) ? 1.0f : 0.0f;
        op[(size_t)t * Hh] = s;
    }
}

// ------------------------------- launch --------------------------------------
extern "C" void kernel_launch(void* const* d_in, const int* in_sizes, int n_in,
                              void* d_out, int out_size)
{
    const float* x     = (const float*)d_in[0];  // [B, T, I]
    const float* W     = (const float*)d_in[1];  // [H, I]
    const float* alpha = (const float*)d_in[2];  // [H]
    const float* u0    = (const float*)d_in[3];  // [B, H]
    const float* s0    = (const float*)d_in[4];  // [B, H]
    float* out = (float*)d_out;

    (void)in_sizes; (void)n_in; (void)out_size;

    cudaFuncSetAttribute(gemm_tf32x3_mma,
                         cudaFuncAttributeMaxDynamicSharedMemorySize, SMEM_TOTAL);

    dim3 grid(Hh / BN, Mm / BM);   // (8, 500)
    gemm_tf32x3_mma<<<grid, 256, SMEM_TOTAL>>>(x, W);

    lif_scan_kernel<<<(Bb * Hh) / 256, 256>>>(alpha, u0, s0, out);
}

// round 5
// speedup vs baseline: 1.1929x; 1.1362x over previous
#include <cuda_runtime.h>
#include <cstdint>

// ---------------------------------------------------------------------------
// LIF layer: Wx = x @ W^T via legacy mma.sync tf32x3-split GEMM (fp32-accurate),
// then per-neuron sequential LIF scan.
// R5: de-serialize accumulator chains (variant-major MMA order) + 2 CTAs/SM.
// ---------------------------------------------------------------------------

static constexpr int Bb = 64;
static constexpr int Tt = 1000;
static constexpr int Ii = 1024;    // K
static constexpr int Hh = 1024;    // N
static constexpr int Mm = Bb * Tt; // 64000

__device__ float g_Wx[(size_t)Mm * Hh];   // 262 MB scratch

// ----------------------------- GEMM config ---------------------------------
static constexpr int BM = 128;
static constexpr int BN = 128;
static constexpr int BK = 16;                  // fp32 elems per chunk
static constexpr int KSTEPS = BK / 8;          // 2 k8-steps per chunk
static constexpr int NCHUNK = Ii / BK;         // 64

// smem fragment layout per variant per k8-step:
//   float2 arr[128][5]  ([row][tig], 5th pads bank conflicts)
//   arr[row][tig] = { M[row][k0+tig], M[row][k0+tig+4] }
static constexpr int ROW_BYTES  = 5 * 8;                // 40
static constexpr int STEP_BYTES = 128 * ROW_BYTES;      // 5120
static constexpr int VAR_BYTES  = KSTEPS * STEP_BYTES;  // 10240
static constexpr int V_AHI = 0;
static constexpr int V_ALO = 1 * VAR_BYTES;
static constexpr int V_BHI = 2 * VAR_BYTES;
static constexpr int V_BLO = 3 * VAR_BYTES;
static constexpr int BUFSZ = 4 * VAR_BYTES;             // 40960
static constexpr int SMEM_TOTAL = 2 * BUFSZ;            // 81920 per CTA

__device__ __forceinline__ uint32_t f2tf32(float a) {
    uint32_t r;
    asm("cvt.rna.tf32.f32 %0, %1;" : "=r"(r) : "f"(a));
    return r;
}

__device__ __forceinline__ void mma_tf32(float* d, const uint32_t* a, const uint32_t* b) {
    asm volatile(
        "mma.sync.aligned.m16n8k8.row.col.f32.tf32.tf32.f32 "
        "{%0,%1,%2,%3}, {%4,%5,%6,%7}, {%8,%9}, {%0,%1,%2,%3};"
        : "+f"(d[0]), "+f"(d[1]), "+f"(d[2]), "+f"(d[3])
        : "r"(a[0]), "r"(a[1]), "r"(a[2]), "r"(a[3]), "r"(b[0]), "r"(b[1]));
}

__global__ __launch_bounds__(256, 2) void gemm_tf32x3_mma(
    const float* __restrict__ A, const float* __restrict__ Bw)
{
    extern __shared__ char smem[];
    const int tid  = threadIdx.x;
    const int wid  = tid >> 5;
    const int lane = tid & 31;
    const int grp  = lane >> 2;     // 0..7
    const int tig  = lane & 3;      // 0..3
    const int warp_m = wid & 1;     // 2 warps in M
    const int warp_n = wid >> 1;    // 4 warps in N
    const int m0w = warp_m * 64;
    const int n0w = warp_n * 32;
    const int bm = blockIdx.y * BM;
    const int bn = blockIdx.x * BN;

    float acc[4][4][4];
#pragma unroll
    for (int i = 0; i < 4; i++)
#pragma unroll
        for (int j = 0; j < 4; j++)
#pragma unroll
            for (int k = 0; k < 4; k++) acc[i][j][k] = 0.0f;

    // fill-thread coordinates: 2 float4 of A and 2 of B per chunk per thread
    int fm[2], fkq[2];
#pragma unroll
    for (int i = 0; i < 2; i++) {
        int f = i * 256 + tid;          // 0..511
        fm[i]  = f >> 2;                // 0..127
        fkq[i] = (f & 3) * 4;           // 0,4,8,12
    }

    float4 va[2], vb[2];

    auto ldg_chunk = [&](int k0) {
#pragma unroll
        for (int i = 0; i < 2; i++) {
            va[i] = *(const float4*)(A  + (size_t)(bm + fm[i]) * Ii + k0 + fkq[i]);
            vb[i] = *(const float4*)(Bw + (size_t)(bn + fm[i]) * Ii + k0 + fkq[i]);
        }
    };

    auto sts_chunk = [&](int buf) {
        char* base = smem + buf * BUFSZ;
#pragma unroll
        for (int i = 0; i < 2; i++) {
            const int s    = fkq[i] >> 3;        // k8 step (0/1)
            const int half = (fkq[i] >> 2) & 1;  // slot in float2
            uint32_t cell = (uint32_t)(s * STEP_BYTES + fm[i] * ROW_BYTES + half * 4);
            const float av[4] = {va[i].x, va[i].y, va[i].z, va[i].w};
            const float bv[4] = {vb[i].x, vb[i].y, vb[i].z, vb[i].w};
#pragma unroll
            for (int j = 0; j < 4; j++) {
                uint32_t ah = f2tf32(av[j]);
                uint32_t al = f2tf32(av[j] - __uint_as_float(ah));
                uint32_t bh = f2tf32(bv[j]);
                uint32_t bl = f2tf32(bv[j] - __uint_as_float(bh));
                *(uint32_t*)(base + V_AHI + cell + j * 8) = ah;
                *(uint32_t*)(base + V_ALO + cell + j * 8) = al;
                *(uint32_t*)(base + V_BHI + cell + j * 8) = bh;
                *(uint32_t*)(base + V_BLO + cell + j * 8) = bl;
            }
        }
    };

    ldg_chunk(0);
    sts_chunk(0);
    __syncthreads();

    for (int c = 0; c < NCHUNK; c++) {
        const int cur = c & 1;
        const char* p = smem + cur * BUFSZ;

        if (c + 1 < NCHUNK) ldg_chunk((c + 1) * BK);  // prefetch overlaps MMA

#pragma unroll
        for (int s = 0; s < KSTEPS; s++) {
            const char* ps = p + s * STEP_BYTES;

            // B fragments: 4 n-tiles x {hi,lo}
            uint32_t bh[4][2], bl[4][2];
#pragma unroll
            for (int nt = 0; nt < 4; nt++) {
                const int n = n0w + nt * 8 + grp;
                float2 h = *(const float2*)(ps + V_BHI + n * ROW_BYTES + tig * 8);
                float2 l = *(const float2*)(ps + V_BLO + n * ROW_BYTES + tig * 8);
                bh[nt][0] = __float_as_uint(h.x); bh[nt][1] = __float_as_uint(h.y);
                bl[nt][0] = __float_as_uint(l.x); bl[nt][1] = __float_as_uint(l.y);
            }

            // process mt in pairs; within a pair, variant-major order gives
            // same-acc reuse distance of 8 MMAs (>= HMMA latency in issue slots)
#pragma unroll
            for (int mp = 0; mp < 2; mp++) {
                uint32_t ah[2][4], al[2][4];
#pragma unroll
                for (int q = 0; q < 2; q++) {
                    const int m = m0w + (mp * 2 + q) * 16 + grp;
                    float2 h0 = *(const float2*)(ps + V_AHI + m * ROW_BYTES + tig * 8);
                    float2 h1 = *(const float2*)(ps + V_AHI + (m + 8) * ROW_BYTES + tig * 8);
                    float2 l0 = *(const float2*)(ps + V_ALO + m * ROW_BYTES + tig * 8);
                    float2 l1 = *(const float2*)(ps + V_ALO + (m + 8) * ROW_BYTES + tig * 8);
                    ah[q][0] = __float_as_uint(h0.x); ah[q][1] = __float_as_uint(h1.x);
                    ah[q][2] = __float_as_uint(h0.y); ah[q][3] = __float_as_uint(h1.y);
                    al[q][0] = __float_as_uint(l0.x); al[q][1] = __float_as_uint(l1.x);
                    al[q][2] = __float_as_uint(l0.y); al[q][3] = __float_as_uint(l1.y);
                }
                // pass 1: hi*hi  (8 independent MMAs)
#pragma unroll
                for (int q = 0; q < 2; q++)
#pragma unroll
                    for (int nt = 0; nt < 4; nt++)
                        mma_tf32(acc[mp * 2 + q][nt], ah[q], bh[nt]);
                // pass 2: hi*lo
#pragma unroll
                for (int q = 0; q < 2; q++)
#pragma unroll
                    for (int nt = 0; nt < 4; nt++)
                        mma_tf32(acc[mp * 2 + q][nt], ah[q], bl[nt]);
                // pass 3: lo*hi
#pragma unroll
                for (int q = 0; q < 2; q++)
#pragma unroll
                    for (int nt = 0; nt < 4; nt++)
                        mma_tf32(acc[mp * 2 + q][nt], al[q], bh[nt]);
            }
        }

        if (c + 1 < NCHUNK) sts_chunk(cur ^ 1);
        __syncthreads();
    }

    // epilogue: registers -> g_Wx (float2 stores)
#pragma unroll
    for (int mt = 0; mt < 4; mt++) {
#pragma unroll
        for (int nt = 0; nt < 4; nt++) {
            const int row = bm + m0w + mt * 16 + grp;
            const int col = bn + n0w + nt * 8 + tig * 2;
            *(float2*)&g_Wx[(size_t)row * Hh + col] =
                make_float2(acc[mt][nt][0], acc[mt][nt][1]);
            *(float2*)&g_Wx[(size_t)(row + 8) * Hh + col] =
                make_float2(acc[mt][nt][2], acc[mt][nt][3]);
        }
    }
}

// ------------------------------- LIF scan ------------------------------------
__global__ __launch_bounds__(256) void lif_scan_kernel(
    const float* __restrict__ alpha,
    const float* __restrict__ u0,
    const float* __restrict__ s0,
    float* __restrict__ out)
{
    const int g = blockIdx.x * blockDim.x + threadIdx.x;
    if (g >= Bb * Hh) return;
    const int h = g & (Hh - 1);
    const int b = g >> 10;

    const float AMIN = 0.81873075307798185867f;  // exp(-1/5)
    const float AMAX = 0.96078943915232320938f;  // exp(-1/25)

    float a = alpha[h];
    a = fminf(fmaxf(a, AMIN), AMAX);
    const float oma = 1.0f - a;

    float u = u0[g];
    float s = s0[g];

    const float* wxp = g_Wx + (size_t)b * Tt * Hh + h;
    float* op = out + (size_t)b * Tt * Hh + h;

#pragma unroll 8
    for (int t = 0; t < Tt; t++) {
        const float wx = wxp[(size_t)t * Hh];
        u = a * (u - s) + oma * wx;
        s = (u > 1.0f) ? 1.0f : 0.0f;
        op[(size_t)t * Hh] = s;
    }
}

// ------------------------------- launch --------------------------------------
extern "C" void kernel_launch(void* const* d_in, const int* in_sizes, int n_in,
                              void* d_out, int out_size)
{
    const float* x     = (const float*)d_in[0];  // [B, T, I]
    const float* W     = (const float*)d_in[1];  // [H, I]
    const float* alpha = (const float*)d_in[2];  // [H]
    const float* u0    = (const float*)d_in[3];  // [B, H]
    const float* s0    = (const float*)d_in[4];  // [B, H]
    float* out = (float*)d_out;

    (void)in_sizes; (void)n_in; (void)out_size;

    cudaFuncSetAttribute(gemm_tf32x3_mma,
                         cudaFuncAttributeMaxDynamicSharedMemorySize, SMEM_TOTAL);

    dim3 grid(Hh / BN, Mm / BM);   // (8, 500)
    gemm_tf32x3_mma<<<grid, 256, SMEM_TOTAL>>>(x, W);

    lif_scan_kernel<<<(Bb * Hh) / 256, 256>>>(alpha, u0, s0, out);
}

// round 7
// speedup vs baseline: 2.1121x; 1.7705x over previous
#include <cuda_runtime.h>
#include <cuda_fp16.h>
#include <cstdint>

// ---------------------------------------------------------------------------
// LIF layer: Wx = x @ W^T via legacy mma.sync fp16x2-split (3-term) GEMM,
// fp32-equivalent accuracy (same 2^-22 dropped-term level as tf32x3, which
// measured rel_err 0.0). W pre-scaled by 2^10 (exact) so its lo-part avoids
// fp16 subnormals; 2^-10 folded into (1-alpha) in the scan (exact).
// ---------------------------------------------------------------------------

static constexpr int Bb = 64;
static constexpr int Tt = 1000;
static constexpr int Ii = 1024;    // K
static constexpr int Hh = 1024;    // N
static constexpr int Mm = Bb * Tt; // 64000

__device__ float g_Wx[(size_t)Mm * Hh];   // 262 MB scratch (holds 2^10 * Wx)

// ----------------------------- GEMM config ---------------------------------
static constexpr int BM = 128;
static constexpr int BN = 128;
static constexpr int BK = 16;                  // one k16 step per chunk
static constexpr int NCHUNK = Ii / BK;         // 64

// smem per variant: cell[row][tig] = uint2{ pack(k=2t,2t+1), pack(k=2t+8,2t+9) }
// row stride 5 uint2 (40B) to break bank conflicts.
static constexpr int ROW_BYTES = 5 * 8;                 // 40
static constexpr int VAR_BYTES = 128 * ROW_BYTES;       // 5120
static constexpr int V_AHI = 0;
static constexpr int V_ALO = 1 * VAR_BYTES;
static constexpr int V_BHI = 2 * VAR_BYTES;
static constexpr int V_BLO = 3 * VAR_BYTES;
static constexpr int BUFSZ = 4 * VAR_BYTES;             // 20480
static constexpr int SMEM_TOTAL = 2 * BUFSZ;            // 40960 per CTA -> 2 CTAs/SM

__device__ __forceinline__ void mma_f16(float* d, const uint32_t* a, const uint32_t* b) {
    asm volatile(
        "mma.sync.aligned.m16n8k16.row.col.f32.f16.f16.f32 "
        "{%0,%1,%2,%3}, {%4,%5,%6,%7}, {%8,%9}, {%0,%1,%2,%3};"
        : "+f"(d[0]), "+f"(d[1]), "+f"(d[2]), "+f"(d[3])
        : "r"(a[0]), "r"(a[1]), "r"(a[2]), "r"(a[3]), "r"(b[0]), "r"(b[1]));
}

__device__ __forceinline__ uint32_t pack_h2(__half a, __half b) {
    return (uint32_t)__half_as_ushort(a) | ((uint32_t)__half_as_ushort(b) << 16);
}

// split float into (hi, lo) fp16 halves
__device__ __forceinline__ void split_f16(float v, __half& hi, __half& lo) {
    hi = __float2half_rn(v);
    lo = __float2half_rn(v - __half2float(hi));
}

__global__ __launch_bounds__(256, 2) void gemm_f16x2_mma(
    const float* __restrict__ A, const float* __restrict__ Bw)
{
    extern __shared__ char smem[];
    const int tid  = threadIdx.x;
    const int wid  = tid >> 5;
    const int lane = tid & 31;
    const int grp  = lane >> 2;     // 0..7
    const int tig  = lane & 3;      // 0..3
    const int warp_m = wid & 1;     // 2 warps in M
    const int warp_n = wid >> 1;    // 4 warps in N
    const int m0w = warp_m * 64;
    const int n0w = warp_n * 32;
    const int bm = blockIdx.y * BM;
    const int bn = blockIdx.x * BN;

    float acc[4][4][4];
#pragma unroll
    for (int i = 0; i < 4; i++)
#pragma unroll
        for (int j = 0; j < 4; j++)
#pragma unroll
            for (int k = 0; k < 4; k++) acc[i][j][k] = 0.0f;

    // fill coordinates: 2 float4 of A and 2 of B per chunk per thread
    int fm[2], fkq[2];
#pragma unroll
    for (int i = 0; i < 2; i++) {
        int f = i * 256 + tid;          // 0..511
        fm[i]  = f >> 2;                // 0..127
        fkq[i] = (f & 3) * 4;           // 0,4,8,12
    }

    float4 va[2], vb[2];

    auto ldg_chunk = [&](int k0) {
#pragma unroll
        for (int i = 0; i < 2; i++) {
            va[i] = *(const float4*)(A  + (size_t)(bm + fm[i]) * Ii + k0 + fkq[i]);
            vb[i] = *(const float4*)(Bw + (size_t)(bn + fm[i]) * Ii + k0 + fkq[i]);
        }
    };

    // float4 at k-quad kq covers half-pairs (kq,kq+1),(kq+2,kq+3):
    // pair (k,k+1), k even: k<8 -> cell[k/2] word0 ; k>=8 -> cell[(k-8)/2] word1
    auto sts_chunk = [&](int buf) {
        char* base = smem + buf * BUFSZ;
#pragma unroll
        for (int i = 0; i < 2; i++) {
            const int word  = (fkq[i] >= 8) ? 4 : 0;           // byte offset of word
            const int cell0 = (fkq[i] & 7) >> 1;               // first cell index
            const uint32_t off = (uint32_t)(fm[i] * ROW_BYTES + cell0 * 8 + word);

            // A: unscaled
            {
                __half h0, l0, h1, l1, h2, l2, h3, l3;
                split_f16(va[i].x, h0, l0); split_f16(va[i].y, h1, l1);
                split_f16(va[i].z, h2, l2); split_f16(va[i].w, h3, l3);
                *(uint32_t*)(base + V_AHI + off)     = pack_h2(h0, h1);
                *(uint32_t*)(base + V_AHI + off + 8) = pack_h2(h2, h3);
                *(uint32_t*)(base + V_ALO + off)     = pack_h2(l0, l1);
                *(uint32_t*)(base + V_ALO + off + 8) = pack_h2(l2, l3);
            }
            // B: scaled by 2^10 so lo stays in fp16 normal range
            {
                __half h0, l0, h1, l1, h2, l2, h3, l3;
                split_f16(vb[i].x * 1024.0f, h0, l0); split_f16(vb[i].y * 1024.0f, h1, l1);
                split_f16(vb[i].z * 1024.0f, h2, l2); split_f16(vb[i].w * 1024.0f, h3, l3);
                *(uint32_t*)(base + V_BHI + off)     = pack_h2(h0, h1);
                *(uint32_t*)(base + V_BHI + off + 8) = pack_h2(h2, h3);
                *(uint32_t*)(base + V_BLO + off)     = pack_h2(l0, l1);
                *(uint32_t*)(base + V_BLO + off + 8) = pack_h2(l2, l3);
            }
        }
    };

    ldg_chunk(0);
    sts_chunk(0);
    __syncthreads();

    for (int c = 0; c < NCHUNK; c++) {
        const int cur = c & 1;
        const char* p = smem + cur * BUFSZ;

        if (c + 1 < NCHUNK) ldg_chunk((c + 1) * BK);   // prefetch overlaps MMA

        // B fragments: 4 n-tiles x {hi,lo}, 1 LDS.64 each (b0=word0, b1=word1)
        uint32_t bh[4][2], bl[4][2];
#pragma unroll
        for (int nt = 0; nt < 4; nt++) {
            const int n = n0w + nt * 8 + grp;
            uint2 h = *(const uint2*)(p + V_BHI + n * ROW_BYTES + tig * 8);
            uint2 l = *(const uint2*)(p + V_BLO + n * ROW_BYTES + tig * 8);
            bh[nt][0] = h.x; bh[nt][1] = h.y;
            bl[nt][0] = l.x; bl[nt][1] = l.y;
        }

        // mt pairs, variant-major: same-acc reuse distance = 8 HMMAs
#pragma unroll
        for (int mp = 0; mp < 2; mp++) {
            uint32_t ah[2][4], al[2][4];
#pragma unroll
            for (int q = 0; q < 2; q++) {
                const int m = m0w + (mp * 2 + q) * 16 + grp;
                uint2 h0 = *(const uint2*)(p + V_AHI + m * ROW_BYTES + tig * 8);
                uint2 h1 = *(const uint2*)(p + V_AHI + (m + 8) * ROW_BYTES + tig * 8);
                uint2 l0 = *(const uint2*)(p + V_ALO + m * ROW_BYTES + tig * 8);
                uint2 l1 = *(const uint2*)(p + V_ALO + (m + 8) * ROW_BYTES + tig * 8);
                ah[q][0] = h0.x; ah[q][1] = h1.x; ah[q][2] = h0.y; ah[q][3] = h1.y;
                al[q][0] = l0.x; al[q][1] = l1.x; al[q][2] = l0.y; al[q][3] = l1.y;
            }
#pragma unroll
            for (int q = 0; q < 2; q++)
#pragma unroll
                for (int nt = 0; nt < 4; nt++)
                    mma_f16(acc[mp * 2 + q][nt], ah[q], bh[nt]);   // hi*hi
#pragma unroll
            for (int q = 0; q < 2; q++)
#pragma unroll
                for (int nt = 0; nt < 4; nt++)
                    mma_f16(acc[mp * 2 + q][nt], ah[q], bl[nt]);   // hi*lo
#pragma unroll
            for (int q = 0; q < 2; q++)
#pragma unroll
                for (int nt = 0; nt < 4; nt++)
                    mma_f16(acc[mp * 2 + q][nt], al[q], bh[nt]);   // lo*hi
        }

        if (c + 1 < NCHUNK) sts_chunk(cur ^ 1);
        __syncthreads();
    }

    // epilogue: registers -> g_Wx (float2 stores)
#pragma unroll
    for (int mt = 0; mt < 4; mt++) {
#pragma unroll
        for (int nt = 0; nt < 4; nt++) {
            const int row = bm + m0w + mt * 16 + grp;
            const int col = bn + n0w + nt * 8 + tig * 2;
            *(float2*)&g_Wx[(size_t)row * Hh + col] =
                make_float2(acc[mt][nt][0], acc[mt][nt][1]);
            *(float2*)&g_Wx[(size_t)(row + 8) * Hh + col] =
                make_float2(acc[mt][nt][2], acc[mt][nt][3]);
        }
    }
}

// ------------------------------- LIF scan ------------------------------------
__global__ __launch_bounds__(256) void lif_scan_kernel(
    const float* __restrict__ alpha,
    const float* __restrict__ u0,
    const float* __restrict__ s0,
    float* __restrict__ out)
{
    const int g = blockIdx.x * blockDim.x + threadIdx.x;
    if (g >= Bb * Hh) return;
    const int h = g & (Hh - 1);
    const int b = g >> 10;

    const float AMIN = 0.81873075307798185867f;  // exp(-1/5)
    const float AMAX = 0.96078943915232320938f;  // exp(-1/25)

    float a = alpha[h];
    a = fminf(fmaxf(a, AMIN), AMAX);
    // g_Wx holds 2^10 * Wx; fold 2^-10 (exact) into (1 - a)
    const float omas = (1.0f - a) * 0.0009765625f;

    float u = u0[g];
    float s = s0[g];

    const float* wxp = g_Wx + (size_t)b * Tt * Hh + h;
    float* op = out + (size_t)b * Tt * Hh + h;

#pragma unroll 8
    for (int t = 0; t < Tt; t++) {
        const float wx = wxp[(size_t)t * Hh];
        u = a * (u - s) + omas * wx;
        s = (u > 1.0f) ? 1.0f : 0.0f;
        op[(size_t)t * Hh] = s;
    }
}

// ------------------------------- launch --------------------------------------
extern "C" void kernel_launch(void* const* d_in, const int* in_sizes, int n_in,
                              void* d_out, int out_size)
{
    const float* x     = (const float*)d_in[0];  // [B, T, I]
    const float* W     = (const float*)d_in[1];  // [H, I]
    const float* alpha = (const float*)d_in[2];  // [H]
    const float* u0    = (const float*)d_in[3];  // [B, H]
    const float* s0    = (const float*)d_in[4];  // [B, H]
    float* out = (float*)d_out;

    (void)in_sizes; (void)n_in; (void)out_size;

    cudaFuncSetAttribute(gemm_f16x2_mma,
                         cudaFuncAttributeMaxDynamicSharedMemorySize, SMEM_TOTAL);

    dim3 grid(Hh / BN, Mm / BM);   // (8, 500)
    gemm_f16x2_mma<<<grid, 256, SMEM_TOTAL>>>(x, W);

    lif_scan_kernel<<<(Bb * Hh) / 256, 256>>>(alpha, u0, s0, out);
}